// round 15
// baseline (speedup 1.0000x reference)
#include <cuda_runtime.h>
#include <cstdint>

// WindowSlice: out[b, t, c] = lerp(x[b, starts[b]+lo(t), c], x[b, starts[b]+lo(t)+1, c], w(t))
// B=64, T=4096, C=128, L = ceil(0.9*T) = 3687.
//
// FINAL (converged; 4 consecutive runs: 47.2 tail / 41.70 / 41.70 / 41.47 us).
// HBM-bound at the practical traffic floor (~200 MB = 128 MB compulsory writes
// + ~72 MB x read misses; pinned by L2 capacity vs the 121 MB x set + write
// stream, non-steerable across 4 policy variants). Effective mixed-stream
// bandwidth 5.5-5.8 TB/s (~70-73% of spec) @NAT clocks.
// Departures scorecard: 0 wins above noise, 4 regressions (MLP 8 x2,
// persistent CTAs, sw pipeline), 3 neutrals (cache policies).
//   - 2 adjacent t-rows per thread -> 4 independent float4 loads (MLP 4)
//   - fully-coalesced 512 B warp segments on both loads and stores
//   - write-through stores (__stwt)
//   - block=1024, grid=4096

#define B_DIM 64
#define T_DIM 4096
#define C_DIM 128
#define L_DIM 3687            // ceil(0.9 * 4096)
#define C4 (C_DIM / 4)        // 32 float4 per row
#define TPB 1024

__device__ __forceinline__ void interp_params(unsigned t, int& lo, float& w)
{
    float step = (float)L_DIM / (float)(T_DIM - 1);
    float q = (float)t * step;
    float tc = fminf(q, (float)(L_DIM - 1));
    float lof = floorf(tc);
    lof = fminf(lof, (float)(L_DIM - 2));
    lo = (int)lof;
    w = tc - lof;
}

__global__ __launch_bounds__(TPB) void window_slice_kernel(
    const float* __restrict__ x,
    const int* __restrict__ starts,
    float* __restrict__ out)
{
    // Each thread handles TWO adjacent t rows at the same c4.
    // idx layout: [b (64)] [tt (2048)] [c4 (32)], t0 = 2*tt, t1 = 2*tt+1.
    unsigned idx = blockIdx.x * (unsigned)TPB + threadIdx.x;
    unsigned c4 = idx & (C4 - 1);             // 0..31 (lane)
    unsigned tt = (idx >> 5) & (T_DIM/2 - 1); // 0..2047
    unsigned b  = idx >> 16;                  // 0..63
    unsigned t0 = tt * 2;
    unsigned t1 = t0 + 1;

    int lo0, lo1;
    float w0, w1;
    interp_params(t0, lo0, w0);
    interp_params(t1, lo1, w1);

    int s = __ldg(&starts[b]);
    long long brow = (long long)b * T_DIM;
    long long base0 = (brow + (s + lo0)) * C_DIM + c4 * 4;
    long long base1 = (brow + (s + lo1)) * C_DIM + c4 * 4;

    // 4 independent loads -> MLP 4
    float4 vlo0 = __ldg((const float4*)(x + base0));
    float4 vhi0 = __ldg((const float4*)(x + base0 + C_DIM));
    float4 vlo1 = __ldg((const float4*)(x + base1));
    float4 vhi1 = __ldg((const float4*)(x + base1 + C_DIM));

    float4 r0, r1;
    r0.x = fmaf(w0, vhi0.x - vlo0.x, vlo0.x);
    r0.y = fmaf(w0, vhi0.y - vlo0.y, vlo0.y);
    r0.z = fmaf(w0, vhi0.z - vlo0.z, vlo0.z);
    r0.w = fmaf(w0, vhi0.w - vlo0.w, vlo0.w);
    r1.x = fmaf(w1, vhi1.x - vlo1.x, vlo1.x);
    r1.y = fmaf(w1, vhi1.y - vlo1.y, vlo1.y);
    r1.z = fmaf(w1, vhi1.z - vlo1.z, vlo1.z);
    r1.w = fmaf(w1, vhi1.w - vlo1.w, vlo1.w);

    // Write-through stores (best-measured).
    float4* o0 = (float4*)out + ((size_t)(b * T_DIM + t0) * C4 + c4);
    float4* o1 = (float4*)out + ((size_t)(b * T_DIM + t1) * C4 + c4);
    __stwt(o0, r0);
    __stwt(o1, r1);
}

extern "C" void kernel_launch(void* const* d_in, const int* in_sizes, int n_in,
                              void* d_out, int out_size)
{
    const float* x = (const float*)d_in[0];
    const int* starts = (const int*)d_in[1];
    float* out = (float*)d_out;

    // threads = B * (T/2) * C4 = 64 * 2048 * 32 = 4,194,304 -> 4096 blocks x 1024
    const unsigned total = B_DIM * (T_DIM / 2) * C4;
    window_slice_kernel<<<total / TPB, TPB>>>(x, starts, out);
}

// round 16
// speedup vs baseline: 1.0054x; 1.0054x over previous
#include <cuda_runtime.h>
#include <cstdint>

// WindowSlice: out[b, t, c] = lerp(x[b, starts[b]+lo(t), c], x[b, starts[b]+lo(t)+1, c], w(t))
// B=64, T=4096, C=128, L = ceil(0.9*T) = 3687.
//
// FINAL (converged; 5 consecutive runs: 47.2 tail / 41.70 / 41.70 / 41.47 /
// 41.70 us; best draw 41.44). HBM-bound at the practical traffic floor
// (~200 MB = 128 MB compulsory writes + ~72 MB x read misses; pinned by L2
// capacity vs the 121 MB x set + write stream, non-steerable across 4 policy
// variants). Effective mixed-stream bandwidth 5.6-5.8 TB/s (~70-73% of spec)
// @NAT clocks. Departures scorecard: 0 wins above noise, 4 regressions
// (MLP 8 x2, persistent CTAs, sw pipeline), 3 neutrals (cache policies).
//   - 2 adjacent t-rows per thread -> 4 independent float4 loads (MLP 4)
//   - fully-coalesced 512 B warp segments on both loads and stores
//   - write-through stores (__stwt)
//   - block=1024, grid=4096

#define B_DIM 64
#define T_DIM 4096
#define C_DIM 128
#define L_DIM 3687            // ceil(0.9 * 4096)
#define C4 (C_DIM / 4)        // 32 float4 per row
#define TPB 1024

__device__ __forceinline__ void interp_params(unsigned t, int& lo, float& w)
{
    float step = (float)L_DIM / (float)(T_DIM - 1);
    float q = (float)t * step;
    float tc = fminf(q, (float)(L_DIM - 1));
    float lof = floorf(tc);
    lof = fminf(lof, (float)(L_DIM - 2));
    lo = (int)lof;
    w = tc - lof;
}

__global__ __launch_bounds__(TPB) void window_slice_kernel(
    const float* __restrict__ x,
    const int* __restrict__ starts,
    float* __restrict__ out)
{
    // Each thread handles TWO adjacent t rows at the same c4.
    // idx layout: [b (64)] [tt (2048)] [c4 (32)], t0 = 2*tt, t1 = 2*tt+1.
    unsigned idx = blockIdx.x * (unsigned)TPB + threadIdx.x;
    unsigned c4 = idx & (C4 - 1);             // 0..31 (lane)
    unsigned tt = (idx >> 5) & (T_DIM/2 - 1); // 0..2047
    unsigned b  = idx >> 16;                  // 0..63
    unsigned t0 = tt * 2;
    unsigned t1 = t0 + 1;

    int lo0, lo1;
    float w0, w1;
    interp_params(t0, lo0, w0);
    interp_params(t1, lo1, w1);

    int s = __ldg(&starts[b]);
    long long brow = (long long)b * T_DIM;
    long long base0 = (brow + (s + lo0)) * C_DIM + c4 * 4;
    long long base1 = (brow + (s + lo1)) * C_DIM + c4 * 4;

    // 4 independent loads -> MLP 4
    float4 vlo0 = __ldg((const float4*)(x + base0));
    float4 vhi0 = __ldg((const float4*)(x + base0 + C_DIM));
    float4 vlo1 = __ldg((const float4*)(x + base1));
    float4 vhi1 = __ldg((const float4*)(x + base1 + C_DIM));

    float4 r0, r1;
    r0.x = fmaf(w0, vhi0.x - vlo0.x, vlo0.x);
    r0.y = fmaf(w0, vhi0.y - vlo0.y, vlo0.y);
    r0.z = fmaf(w0, vhi0.z - vlo0.z, vlo0.z);
    r0.w = fmaf(w0, vhi0.w - vlo0.w, vlo0.w);
    r1.x = fmaf(w1, vhi1.x - vlo1.x, vlo1.x);
    r1.y = fmaf(w1, vhi1.y - vlo1.y, vlo1.y);
    r1.z = fmaf(w1, vhi1.z - vlo1.z, vlo1.z);
    r1.w = fmaf(w1, vhi1.w - vlo1.w, vlo1.w);

    // Write-through stores (best-measured).
    float4* o0 = (float4*)out + ((size_t)(b * T_DIM + t0) * C4 + c4);
    float4* o1 = (float4*)out + ((size_t)(b * T_DIM + t1) * C4 + c4);
    __stwt(o0, r0);
    __stwt(o1, r1);
}

extern "C" void kernel_launch(void* const* d_in, const int* in_sizes, int n_in,
                              void* d_out, int out_size)
{
    const float* x = (const float*)d_in[0];
    const int* starts = (const int*)d_in[1];
    float* out = (float*)d_out;

    // threads = B * (T/2) * C4 = 64 * 2048 * 32 = 4,194,304 -> 4096 blocks x 1024
    const unsigned total = B_DIM * (T_DIM / 2) * C4;
    window_slice_kernel<<<total / TPB, TPB>>>(x, starts, out);
}